// round 1
// baseline (speedup 1.0000x reference)
#include <cuda_runtime.h>
#include <math.h>

#define N_NODES 100000
#define N_EDGES 3200000
#define IN_CH   602
#define HID     16
#define OUT_CH  41

// Scratch (device globals; no allocation allowed)
__device__ float g_h1  [N_NODES * HID];
__device__ float g_agg1[N_NODES * HID];
__device__ float g_r   [N_NODES * HID];
__device__ float g_agg2[N_NODES * HID];
__device__ float g_cnt [N_NODES];

// ---------------------------------------------------------------------------
// K1: h1[N,16] = x[N,602] @ W1[602,16].  Warp per row; W1 in smem as float4.
// ---------------------------------------------------------------------------
__global__ void gemm1_kernel(const float* __restrict__ x,
                             const float* __restrict__ W1,
                             float* __restrict__ h1) {
    __shared__ float4 ws[IN_CH * 4];   // W1 row k -> ws[4k..4k+3]
    for (int i = threadIdx.x; i < IN_CH * 4; i += blockDim.x)
        ws[i] = ((const float4*)W1)[i];
    __syncthreads();

    int row  = (blockIdx.x * blockDim.x + threadIdx.x) >> 5;
    int lane = threadIdx.x & 31;
    if (row >= N_NODES) return;

    const float* xr = x + (size_t)row * IN_CH;
    float a0=0,a1=0,a2=0,a3=0,a4=0,a5=0,a6=0,a7=0,
          a8=0,a9=0,a10=0,a11=0,a12=0,a13=0,a14=0,a15=0;

    for (int k = lane; k < IN_CH; k += 32) {
        float xv = __ldg(xr + k);
        float4 w0 = ws[k*4+0], w1 = ws[k*4+1], w2 = ws[k*4+2], w3 = ws[k*4+3];
        a0  += xv * w0.x;  a1  += xv * w0.y;  a2  += xv * w0.z;  a3  += xv * w0.w;
        a4  += xv * w1.x;  a5  += xv * w1.y;  a6  += xv * w1.z;  a7  += xv * w1.w;
        a8  += xv * w2.x;  a9  += xv * w2.y;  a10 += xv * w2.z;  a11 += xv * w2.w;
        a12 += xv * w3.x;  a13 += xv * w3.y;  a14 += xv * w3.z;  a15 += xv * w3.w;
    }

    float acc[16] = {a0,a1,a2,a3,a4,a5,a6,a7,a8,a9,a10,a11,a12,a13,a14,a15};
    float out = 0.f;
    #pragma unroll
    for (int j = 0; j < 16; j++) {
        float v = acc[j];
        v += __shfl_xor_sync(0xffffffffu, v, 16);
        v += __shfl_xor_sync(0xffffffffu, v, 8);
        v += __shfl_xor_sync(0xffffffffu, v, 4);
        v += __shfl_xor_sync(0xffffffffu, v, 2);
        v += __shfl_xor_sync(0xffffffffu, v, 1);
        if (lane == j) out = v;
    }
    if (lane < 16) h1[(size_t)row * 16 + lane] = out;
}

// ---------------------------------------------------------------------------
// K2/K4: edge scatter.  agg[dst] += h[src] (16 floats via 4x red.v4.f32).
// Optionally also counts degree into cnt (pass nullptr to skip).
// ---------------------------------------------------------------------------
__global__ void scatter_kernel(const float* __restrict__ h,
                               const int*  __restrict__ src,
                               const int*  __restrict__ dst,
                               float* __restrict__ agg,
                               float* __restrict__ cnt) {
    int e = blockIdx.x * blockDim.x + threadIdx.x;
    if (e >= N_EDGES) return;
    int s = src[e];
    int d = dst[e];
    const float4* hv = (const float4*)(h + (size_t)s * 16);
    float4 v0 = __ldg(hv + 0);
    float4 v1 = __ldg(hv + 1);
    float4 v2 = __ldg(hv + 2);
    float4 v3 = __ldg(hv + 3);
    float* ap = agg + (size_t)d * 16;
    asm volatile("red.global.add.v4.f32 [%0], {%1,%2,%3,%4};"
                 :: "l"(ap +  0), "f"(v0.x), "f"(v0.y), "f"(v0.z), "f"(v0.w) : "memory");
    asm volatile("red.global.add.v4.f32 [%0], {%1,%2,%3,%4};"
                 :: "l"(ap +  4), "f"(v1.x), "f"(v1.y), "f"(v1.z), "f"(v1.w) : "memory");
    asm volatile("red.global.add.v4.f32 [%0], {%1,%2,%3,%4};"
                 :: "l"(ap +  8), "f"(v2.x), "f"(v2.y), "f"(v2.z), "f"(v2.w) : "memory");
    asm volatile("red.global.add.v4.f32 [%0], {%1,%2,%3,%4};"
                 :: "l"(ap + 12), "f"(v3.x), "f"(v3.y), "f"(v3.z), "f"(v3.w) : "memory");
    if (cnt != nullptr) {
        asm volatile("red.global.add.f32 [%0], %1;"
                     :: "l"(cnt + d), "f"(1.0f) : "memory");
    }
}

// ---------------------------------------------------------------------------
// K3: r = relu(agg1 / max(cnt,1) + b1).  4 threads per node (float4 each).
// ---------------------------------------------------------------------------
__global__ void relu_mean_kernel(const float* __restrict__ b1,
                                 const float* __restrict__ agg1,
                                 const float* __restrict__ cnt,
                                 float* __restrict__ r) {
    int idx = blockIdx.x * blockDim.x + threadIdx.x;
    if (idx >= N_NODES * 4) return;
    int node = idx >> 2;
    int q    = idx & 3;
    float c   = fmaxf(cnt[node], 1.0f);
    float inv = 1.0f / c;
    float4 v  = ((const float4*)agg1)[idx];
    float4 bb = __ldg(((const float4*)b1) + q);
    v.x = fmaxf(v.x * inv + bb.x, 0.0f);
    v.y = fmaxf(v.y * inv + bb.y, 0.0f);
    v.z = fmaxf(v.z * inv + bb.z, 0.0f);
    v.w = fmaxf(v.w * inv + bb.w, 0.0f);
    ((float4*)r)[idx] = v;
}

// ---------------------------------------------------------------------------
// K5: out = log_softmax( (agg2/max(cnt,1)) @ W2 + b2 ).  Thread per node.
// ---------------------------------------------------------------------------
__global__ void out_kernel(const float* __restrict__ W2,
                           const float* __restrict__ b2,
                           const float* __restrict__ agg2,
                           const float* __restrict__ cnt,
                           float* __restrict__ out) {
    __shared__ float w2s[HID * OUT_CH];
    __shared__ float b2s[OUT_CH];
    for (int i = threadIdx.x; i < HID * OUT_CH; i += blockDim.x) w2s[i] = W2[i];
    for (int i = threadIdx.x; i < OUT_CH;       i += blockDim.x) b2s[i] = b2[i];
    __syncthreads();

    int n = blockIdx.x * blockDim.x + threadIdx.x;
    if (n >= N_NODES) return;

    float c   = fmaxf(cnt[n], 1.0f);
    float inv = 1.0f / c;

    const float4* av = (const float4*)(agg2 + (size_t)n * 16);
    float4 m0 = av[0], m1 = av[1], m2 = av[2], m3 = av[3];
    float m[16] = { m0.x*inv, m0.y*inv, m0.z*inv, m0.w*inv,
                    m1.x*inv, m1.y*inv, m1.z*inv, m1.w*inv,
                    m2.x*inv, m2.y*inv, m2.z*inv, m2.w*inv,
                    m3.x*inv, m3.y*inv, m3.z*inv, m3.w*inv };

    float o[OUT_CH];
    #pragma unroll
    for (int j = 0; j < OUT_CH; j++) {
        float s = b2s[j];
        #pragma unroll
        for (int k = 0; k < HID; k++)
            s += m[k] * w2s[k * OUT_CH + j];
        o[j] = s;
    }

    float mx = o[0];
    #pragma unroll
    for (int j = 1; j < OUT_CH; j++) mx = fmaxf(mx, o[j]);
    float sum = 0.0f;
    #pragma unroll
    for (int j = 0; j < OUT_CH; j++) sum += __expf(o[j] - mx);
    float ls = __logf(sum) + mx;

    float* op = out + (size_t)n * OUT_CH;
    #pragma unroll
    for (int j = 0; j < OUT_CH; j++) op[j] = o[j] - ls;
}

// ---------------------------------------------------------------------------
extern "C" void kernel_launch(void* const* d_in, const int* in_sizes, int n_in,
                              void* d_out, int out_size) {
    const float* x  = (const float*)d_in[0];
    const int*   ei = (const int*)  d_in[1];
    const float* W1 = (const float*)d_in[2];
    const float* b1 = (const float*)d_in[3];
    const float* W2 = (const float*)d_in[4];
    const float* b2 = (const float*)d_in[5];
    float* out = (float*)d_out;

    const int* src = ei;
    const int* dst = ei + N_EDGES;

    float *p_h1, *p_agg1, *p_r, *p_agg2, *p_cnt;
    cudaGetSymbolAddress((void**)&p_h1,   g_h1);
    cudaGetSymbolAddress((void**)&p_agg1, g_agg1);
    cudaGetSymbolAddress((void**)&p_r,    g_r);
    cudaGetSymbolAddress((void**)&p_agg2, g_agg2);
    cudaGetSymbolAddress((void**)&p_cnt,  g_cnt);

    cudaMemsetAsync(p_agg1, 0, sizeof(float) * N_NODES * HID);
    cudaMemsetAsync(p_agg2, 0, sizeof(float) * N_NODES * HID);
    cudaMemsetAsync(p_cnt,  0, sizeof(float) * N_NODES);

    // K1: h1 = x @ W1  (warp per row)
    gemm1_kernel<<<(N_NODES * 32) / 256, 256>>>(x, W1, p_h1);

    // K2: agg1[dst] += h1[src]; cnt[dst] += 1
    scatter_kernel<<<(N_EDGES + 255) / 256, 256>>>(p_h1, src, dst, p_agg1, p_cnt);

    // K3: r = relu(agg1/max(cnt,1) + b1)
    relu_mean_kernel<<<(N_NODES * 4 + 255) / 256, 256>>>(b1, p_agg1, p_cnt, p_r);

    // K4: agg2[dst] += r[src]   (width-16 scatter; W2 applied after, by linearity)
    scatter_kernel<<<(N_EDGES + 255) / 256, 256>>>(p_r, src, dst, p_agg2, nullptr);

    // K5: out = log_softmax(agg2/max(cnt,1) @ W2 + b2)
    out_kernel<<<(N_NODES + 255) / 256, 256>>>(W2, b2, p_agg2, p_cnt, out);
}

// round 2
// speedup vs baseline: 1.8731x; 1.8731x over previous
#include <cuda_runtime.h>
#include <math.h>

#define N_NODES 100000
#define N_EDGES 3200000
#define IN_CH   602
#define HID     16
#define OUT_CH  41

#define M_TILE  256
#define K_CHUNK 32

// Scratch (device globals; no allocation allowed)
__device__ float g_h1  [N_NODES * HID];
__device__ float g_agg1[N_NODES * HID];
__device__ float g_r   [N_NODES * HID];
__device__ float g_agg2[N_NODES * HID];
__device__ float g_cnt [N_NODES];

// ---------------------------------------------------------------------------
// K1: h1[N,16] = x[N,602] @ W1[602,16].
// Tiled register-blocked SGEMM: block = 256 rows x 16 cols, K chunks of 32.
// x staged k-major in smem (conflict-free strided reads); W1 chunk broadcast.
// Each thread: 8 rows x 2 cols -> 8 LDS + 16 FMA per k-step.
// ---------------------------------------------------------------------------
__global__ __launch_bounds__(256)
void gemm1_tiled(const float* __restrict__ x,
                 const float* __restrict__ W1,
                 float* __restrict__ h1) {
    __shared__ float xs[K_CHUNK][M_TILE + 1];  // +1 pad: conflict-free k-major writes
    __shared__ float ws[K_CHUNK][HID];

    const int tid      = threadIdx.x;
    const int row_base = blockIdx.x * M_TILE;
    const int tr = tid & 31;         // row lane within tile (rows tr + 32*i)
    const int tc = (tid >> 5) * 2;   // column pair (0,2,...,14)

    float acc[8][2];
    #pragma unroll
    for (int i = 0; i < 8; i++) { acc[i][0] = 0.f; acc[i][1] = 0.f; }

    for (int kc = 0; kc < IN_CH; kc += K_CHUNK) {
        // Load x tile: 256 rows x 32 k, warp reads one full row-chunk (coalesced 128B)
        #pragma unroll
        for (int i = 0; i < 32; i++) {
            int g = i * 256 + tid;
            int r = g >> 5;
            int k = g & 31;
            int gk = kc + k;
            float v = 0.f;
            if (gk < IN_CH) {
                int grow = row_base + r;
                int cr = (grow < N_NODES) ? grow : 0;   // clamp; garbage rows never stored
                v = __ldg(x + (size_t)cr * IN_CH + gk);
            }
            xs[k][r] = v;
        }
        // Load W1 chunk: 32 x 16
        #pragma unroll
        for (int i = 0; i < 2; i++) {
            int g = i * 256 + tid;
            int k = g >> 4;
            int c = g & 15;
            int gk = kc + k;
            ws[k][c] = (gk < IN_CH) ? W1[(size_t)gk * HID + c] : 0.f;
        }
        __syncthreads();

        #pragma unroll
        for (int k = 0; k < K_CHUNK; k++) {
            float w0 = ws[k][tc];        // warp-broadcast
            float w1 = ws[k][tc + 1];
            #pragma unroll
            for (int i = 0; i < 8; i++) {
                float xv = xs[k][tr + 32 * i];   // stride-1 across lanes: conflict-free
                acc[i][0] += xv * w0;
                acc[i][1] += xv * w1;
            }
        }
        __syncthreads();
    }

    #pragma unroll
    for (int i = 0; i < 8; i++) {
        int row = row_base + tr + 32 * i;
        if (row < N_NODES) {
            float2 v = make_float2(acc[i][0], acc[i][1]);
            *(float2*)(h1 + (size_t)row * 16 + tc) = v;
        }
    }
}

// ---------------------------------------------------------------------------
// K2/K4: edge scatter.  agg[dst] += h[src] (16 floats via 4x red.v4.f32).
// Optionally also counts degree into cnt (pass nullptr to skip).
// ---------------------------------------------------------------------------
__global__ void scatter_kernel(const float* __restrict__ h,
                               const int*  __restrict__ src,
                               const int*  __restrict__ dst,
                               float* __restrict__ agg,
                               float* __restrict__ cnt) {
    int e = blockIdx.x * blockDim.x + threadIdx.x;
    if (e >= N_EDGES) return;
    int s = src[e];
    int d = dst[e];
    const float4* hv = (const float4*)(h + (size_t)s * 16);
    float4 v0 = __ldg(hv + 0);
    float4 v1 = __ldg(hv + 1);
    float4 v2 = __ldg(hv + 2);
    float4 v3 = __ldg(hv + 3);
    float* ap = agg + (size_t)d * 16;
    asm volatile("red.global.add.v4.f32 [%0], {%1,%2,%3,%4};"
                 :: "l"(ap +  0), "f"(v0.x), "f"(v0.y), "f"(v0.z), "f"(v0.w) : "memory");
    asm volatile("red.global.add.v4.f32 [%0], {%1,%2,%3,%4};"
                 :: "l"(ap +  4), "f"(v1.x), "f"(v1.y), "f"(v1.z), "f"(v1.w) : "memory");
    asm volatile("red.global.add.v4.f32 [%0], {%1,%2,%3,%4};"
                 :: "l"(ap +  8), "f"(v2.x), "f"(v2.y), "f"(v2.z), "f"(v2.w) : "memory");
    asm volatile("red.global.add.v4.f32 [%0], {%1,%2,%3,%4};"
                 :: "l"(ap + 12), "f"(v3.x), "f"(v3.y), "f"(v3.z), "f"(v3.w) : "memory");
    if (cnt != nullptr) {
        asm volatile("red.global.add.f32 [%0], %1;"
                     :: "l"(cnt + d), "f"(1.0f) : "memory");
    }
}

// ---------------------------------------------------------------------------
// K3: r = relu(agg1 / max(cnt,1) + b1).  4 threads per node (float4 each).
// ---------------------------------------------------------------------------
__global__ void relu_mean_kernel(const float* __restrict__ b1,
                                 const float* __restrict__ agg1,
                                 const float* __restrict__ cnt,
                                 float* __restrict__ r) {
    int idx = blockIdx.x * blockDim.x + threadIdx.x;
    if (idx >= N_NODES * 4) return;
    int node = idx >> 2;
    int q    = idx & 3;
    float c   = fmaxf(cnt[node], 1.0f);
    float inv = 1.0f / c;
    float4 v  = ((const float4*)agg1)[idx];
    float4 bb = __ldg(((const float4*)b1) + q);
    v.x = fmaxf(v.x * inv + bb.x, 0.0f);
    v.y = fmaxf(v.y * inv + bb.y, 0.0f);
    v.z = fmaxf(v.z * inv + bb.z, 0.0f);
    v.w = fmaxf(v.w * inv + bb.w, 0.0f);
    ((float4*)r)[idx] = v;
}

// ---------------------------------------------------------------------------
// K5: out = log_softmax( (agg2/max(cnt,1)) @ W2 + b2 ).  Thread per node.
// ---------------------------------------------------------------------------
__global__ void out_kernel(const float* __restrict__ W2,
                           const float* __restrict__ b2,
                           const float* __restrict__ agg2,
                           const float* __restrict__ cnt,
                           float* __restrict__ out) {
    __shared__ float w2s[HID * OUT_CH];
    __shared__ float b2s[OUT_CH];
    for (int i = threadIdx.x; i < HID * OUT_CH; i += blockDim.x) w2s[i] = W2[i];
    for (int i = threadIdx.x; i < OUT_CH;       i += blockDim.x) b2s[i] = b2[i];
    __syncthreads();

    int n = blockIdx.x * blockDim.x + threadIdx.x;
    if (n >= N_NODES) return;

    float c   = fmaxf(cnt[n], 1.0f);
    float inv = 1.0f / c;

    const float4* av = (const float4*)(agg2 + (size_t)n * 16);
    float4 m0 = av[0], m1 = av[1], m2 = av[2], m3 = av[3];
    float m[16] = { m0.x*inv, m0.y*inv, m0.z*inv, m0.w*inv,
                    m1.x*inv, m1.y*inv, m1.z*inv, m1.w*inv,
                    m2.x*inv, m2.y*inv, m2.z*inv, m2.w*inv,
                    m3.x*inv, m3.y*inv, m3.z*inv, m3.w*inv };

    float o[OUT_CH];
    #pragma unroll
    for (int j = 0; j < OUT_CH; j++) {
        float s = b2s[j];
        #pragma unroll
        for (int k = 0; k < HID; k++)
            s += m[k] * w2s[k * OUT_CH + j];
        o[j] = s;
    }

    float mx = o[0];
    #pragma unroll
    for (int j = 1; j < OUT_CH; j++) mx = fmaxf(mx, o[j]);
    float sum = 0.0f;
    #pragma unroll
    for (int j = 0; j < OUT_CH; j++) sum += __expf(o[j] - mx);
    float ls = __logf(sum) + mx;

    float* op = out + (size_t)n * OUT_CH;
    #pragma unroll
    for (int j = 0; j < OUT_CH; j++) op[j] = o[j] - ls;
}

// ---------------------------------------------------------------------------
extern "C" void kernel_launch(void* const* d_in, const int* in_sizes, int n_in,
                              void* d_out, int out_size) {
    const float* x  = (const float*)d_in[0];
    const int*   ei = (const int*)  d_in[1];
    const float* W1 = (const float*)d_in[2];
    const float* b1 = (const float*)d_in[3];
    const float* W2 = (const float*)d_in[4];
    const float* b2 = (const float*)d_in[5];
    float* out = (float*)d_out;

    const int* src = ei;
    const int* dst = ei + N_EDGES;

    float *p_h1, *p_agg1, *p_r, *p_agg2, *p_cnt;
    cudaGetSymbolAddress((void**)&p_h1,   g_h1);
    cudaGetSymbolAddress((void**)&p_agg1, g_agg1);
    cudaGetSymbolAddress((void**)&p_r,    g_r);
    cudaGetSymbolAddress((void**)&p_agg2, g_agg2);
    cudaGetSymbolAddress((void**)&p_cnt,  g_cnt);

    cudaMemsetAsync(p_agg1, 0, sizeof(float) * N_NODES * HID);
    cudaMemsetAsync(p_agg2, 0, sizeof(float) * N_NODES * HID);
    cudaMemsetAsync(p_cnt,  0, sizeof(float) * N_NODES);

    // K1: h1 = x @ W1  (tiled SGEMM, 256 rows/block)
    gemm1_tiled<<<(N_NODES + M_TILE - 1) / M_TILE, 256>>>(x, W1, p_h1);

    // K2: agg1[dst] += h1[src]; cnt[dst] += 1
    scatter_kernel<<<(N_EDGES + 255) / 256, 256>>>(p_h1, src, dst, p_agg1, p_cnt);

    // K3: r = relu(agg1/max(cnt,1) + b1)
    relu_mean_kernel<<<(N_NODES * 4 + 255) / 256, 256>>>(b1, p_agg1, p_cnt, p_r);

    // K4: agg2[dst] += r[src]   (width-16 scatter; W2 applied after, by linearity)
    scatter_kernel<<<(N_EDGES + 255) / 256, 256>>>(p_r, src, dst, p_agg2, nullptr);

    // K5: out = log_softmax(agg2/max(cnt,1) @ W2 + b2)
    out_kernel<<<(N_NODES + 255) / 256, 256>>>(W2, b2, p_agg2, p_cnt, out);
}